// round 3
// baseline (speedup 1.0000x reference)
#include <cuda_runtime.h>
#include <cstdint>

// ALNNLayer fused kernel, cp.async depth-2 pipelined.
// Shapes: X,T,M,DT: [B=64, L=200, D=64]; alpha: [K=13]; w_v,b_t: [K,L,D];
//         w_t: [K,L,D,4]; b_v: [K,1,D]; out: [B,K,D].
// Per (b,k,l,d):
//   kern  = exp(-relu(alpha_k) * |T - 4k|)
//   inten = kern * relu(X)
//   lat   = relu(wt0*X + wt1*DT + wt2*inten + wt3*M + 4*b_t)
//   out[b,k,d] = relu( sum_l w_v*lat + 200*b_v[k,d] )

#define KREF 13
#define LN   200
#define DN   64
#define BN   64
#define BT   8            // b-tile per block
#define LC   5            // l-steps per block
#define NCHUNK (LN / LC)  // 40
#define NBT    (BN / BT)  // 8
#define NTHREADS 416      // 13 warps

// smem chunk counts (16B units) per stage
#define NC_IN  512        // 4 arrays * 8 b * 64 d floats / 4
#define NC_WV  208        // 13 k * 64 / 4
#define NC_BT  208
#define NC_WT  832        // 13 k * 256 / 4
#define NC_TOT (NC_IN + NC_WV + NC_BT + NC_WT)   // 1760

// scratch[chunk][b][k][d]
__device__ float g_scratch[NCHUNK * BN * KREF * DN];

__device__ __forceinline__ void cp16(float* dst, const float* src) {
    uint32_t d32 = (uint32_t)__cvta_generic_to_shared(dst);
    asm volatile("cp.async.cg.shared.global [%0], [%1], 16;" :: "r"(d32), "l"(src));
}
__device__ __forceinline__ void cp_commit() {
    asm volatile("cp.async.commit_group;");
}
__device__ __forceinline__ void cp_wait1() {
    asm volatile("cp.async.wait_group 1;");
}

__global__ __launch_bounds__(NTHREADS, 2)
void alnn_main(const float* __restrict__ X,
               const float* __restrict__ T,
               const float* __restrict__ M,
               const float* __restrict__ DT,
               const float* __restrict__ alpha,
               const float* __restrict__ w_v,
               const float* __restrict__ w_t,
               const float* __restrict__ b_t)
{
    // smem: in_buf[st][arr][bi][d], w_buf[st][k][384] (0..63 wv, 64..127 bt, 128..383 wt[d][4])
    __shared__ __align__(16) float in_buf[2][4][BT][DN];
    __shared__ __align__(16) float w_buf[2][KREF][384];

    const int chunk = blockIdx.x;        // 0..39
    const int btile = blockIdx.y;        // 0..7
    const int tid   = threadIdx.x;
    const int k     = tid >> 5;          // warp id = k (0..12)
    const int lane  = tid & 31;
    const int d0    = lane * 2;
    const int l0    = chunk * LC;
    const int b0    = btile * BT;

    const float a  = fmaxf(__ldg(alpha + k), 0.0f);
    const float rt = 4.0f * (float)k;

    const float* in_ptr[4] = { X, T, M, DT };

    // ---- copy stage for time-step l into smem stage st ----
    auto stage_copy = [&](int l, int st) {
        for (int c = tid; c < NC_TOT; c += NTHREADS) {
            const float* src;
            float* dst;
            if (c < NC_IN) {
                const int row = c >> 4;        // 0..31
                const int arr = row >> 3;
                const int bi  = row & 7;
                const int off = (c & 15) * 4;
                src = in_ptr[arr] + ((size_t)(b0 + bi) * LN + l) * DN + off;
                dst = &in_buf[st][arr][bi][off];
            } else if (c < NC_IN + NC_WV) {
                const int cc = c - NC_IN;
                const int k2 = cc >> 4;
                const int off = (cc & 15) * 4;
                src = w_v + ((size_t)k2 * LN + l) * DN + off;
                dst = &w_buf[st][k2][off];
            } else if (c < NC_IN + NC_WV + NC_BT) {
                const int cc = c - (NC_IN + NC_WV);
                const int k2 = cc >> 4;
                const int off = (cc & 15) * 4;
                src = b_t + ((size_t)k2 * LN + l) * DN + off;
                dst = &w_buf[st][k2][64 + off];
            } else {
                const int cc = c - (NC_IN + NC_WV + NC_BT);
                const int k2 = cc >> 6;
                const int off = (cc & 63) * 4;
                src = w_t + ((size_t)k2 * LN + l) * (DN * 4) + off;
                dst = &w_buf[st][k2][128 + off];
            }
            cp16(dst, src);
        }
    };

    float accx[BT], accy[BT];
    #pragma unroll
    for (int i = 0; i < BT; i++) { accx[i] = 0.0f; accy[i] = 0.0f; }

    // prologue: stage l0 into buffer 0
    stage_copy(l0, 0);
    cp_commit();

    int st = 0;
    for (int li = 0; li < LC; ++li) {
        if (li + 1 < LC) stage_copy(l0 + li + 1, st ^ 1);
        cp_commit();
        cp_wait1();            // stage st is complete
        __syncthreads();       // visible to all warps

        // ---- compute from stage st ----
        const float2 wv  = *reinterpret_cast<const float2*>(&w_buf[st][k][d0]);
        const float2 btv = *reinterpret_cast<const float2*>(&w_buf[st][k][64 + d0]);
        const float4 wt0 = *reinterpret_cast<const float4*>(&w_buf[st][k][128 + d0 * 4]);
        const float4 wt1 = *reinterpret_cast<const float4*>(&w_buf[st][k][128 + d0 * 4 + 4]);
        const float bt4x = 4.0f * btv.x;
        const float bt4y = 4.0f * btv.y;

        #pragma unroll
        for (int bi = 0; bi < BT; bi++) {
            const float2 x  = *reinterpret_cast<const float2*>(&in_buf[st][0][bi][d0]);
            const float2 t  = *reinterpret_cast<const float2*>(&in_buf[st][1][bi][d0]);
            const float2 m  = *reinterpret_cast<const float2*>(&in_buf[st][2][bi][d0]);
            const float2 dt = *reinterpret_cast<const float2*>(&in_buf[st][3][bi][d0]);

            const float in0 = __expf(-a * fabsf(t.x - rt)) * fmaxf(x.x, 0.0f);
            const float in1 = __expf(-a * fabsf(t.y - rt)) * fmaxf(x.y, 0.0f);

            float s0 = fmaf(wt0.x, x.x,
                       fmaf(wt0.y, dt.x,
                       fmaf(wt0.z, in0,
                       fmaf(wt0.w, m.x, bt4x))));
            float s1 = fmaf(wt1.x, x.y,
                       fmaf(wt1.y, dt.y,
                       fmaf(wt1.z, in1,
                       fmaf(wt1.w, m.y, bt4y))));

            accx[bi] = fmaf(wv.x, fmaxf(s0, 0.0f), accx[bi]);
            accy[bi] = fmaf(wv.y, fmaxf(s1, 0.0f), accy[bi]);
        }

        __syncthreads();       // all reads of stage st done before it is overwritten
        st ^= 1;
    }

    // scratch[chunk][b][k][d]
    #pragma unroll
    for (int bi = 0; bi < BT; bi++) {
        float2 v = make_float2(accx[bi], accy[bi]);
        *reinterpret_cast<float2*>(
            g_scratch + ((size_t)(chunk * BN + b0 + bi) * KREF + k) * DN + d0) = v;
    }
}

// finalize: block per (b,k); 4 chunk-groups x 64 d threads
__global__ __launch_bounds__(256)
void alnn_finalize(const float* __restrict__ b_v, float* __restrict__ out)
{
    const int bk = blockIdx.x;           // b*KREF + k
    const int b  = bk / KREF;
    const int k  = bk - b * KREF;
    const int d  = threadIdx.x & 63;
    const int cg = threadIdx.x >> 6;     // 0..3

    float s = 0.0f;
    #pragma unroll
    for (int c = 0; c < NCHUNK / 4; c++) {
        const int ch = cg * (NCHUNK / 4) + c;
        s += g_scratch[((size_t)(ch * BN + b) * KREF + k) * DN + d];
    }

    __shared__ float red[4][DN];
    red[cg][d] = s;
    __syncthreads();

    if (threadIdx.x < DN) {
        const float tot = red[0][d] + red[1][d] + red[2][d] + red[3][d];
        const float bv  = __ldg(b_v + k * DN + d);
        out[bk * DN + d] = fmaxf(fmaf(200.0f, bv, tot), 0.0f);
    }
}

extern "C" void kernel_launch(void* const* d_in, const int* in_sizes, int n_in,
                              void* d_out, int out_size)
{
    // metadata order: X, T, M, DT, alpha, w_v, w_t, b_v, b_t
    const float* X     = (const float*)d_in[0];
    const float* T     = (const float*)d_in[1];
    const float* M     = (const float*)d_in[2];
    const float* DT    = (const float*)d_in[3];
    const float* alpha = (const float*)d_in[4];
    const float* w_v   = (const float*)d_in[5];
    const float* w_t   = (const float*)d_in[6];
    const float* b_v   = (const float*)d_in[7];
    const float* b_t   = (const float*)d_in[8];
    float* out = (float*)d_out;

    dim3 grid(NCHUNK, NBT);
    alnn_main<<<grid, NTHREADS>>>(X, T, M, DT, alpha, w_v, w_t, b_t);
    alnn_finalize<<<BN * KREF, 256>>>(b_v, out);
}